// round 17
// baseline (speedup 1.0000x reference)
#include <cuda_runtime.h>
#include <math.h>

#define N        96
#define NT       384     // pre_k threads per CTA
#define NT2      768     // MPM threads per CTA (24 warps)
#define NN       9216
#define ATS      97      // padded stride for transposed matrices in smem
#define IN_DIM   64
#define HID      256
#define ZD       64
#define E        1024
#define NUM_LOGITS 4656
#define ITERS    50
#define UTRI     4560
#define DMAX     32      // padded neighbor-list capacity

#define PREF_L2(p) asm volatile("prefetch.global.L2 [%0];" :: "l"(p))

// ---------------- device scratch (no allocations allowed) ----------------
__device__ float g_Ht[N * HID];       // layer-1 activations, TRANSPOSED
__device__ float g_gv[HID];
__device__ float g_B[NN];
__device__ float g_degA[N];
__device__ int   g_deg[N];
__device__ int   g_nbr[NN];
__device__ float g_M[2][NN + N];      // +1 zero row for padded neighbors
__device__ float g_part[16];          // per-CTA sum-of-squares partials

#define C_ARRIVE() asm volatile("barrier.cluster.arrive.aligned;" ::: "memory")
#define C_WAIT()   asm volatile("barrier.cluster.wait.aligned;"   ::: "memory")
#define CSYNC() do { C_ARRIVE(); C_WAIT(); } while (0)

// ======================= PRE KERNEL (GCN + VAE + decoder) ==================
// One 16-CTA cluster, 2 cluster syncs. Every CTA redundantly builds A_norm^T
// in smem from edge_index (directed! A_norm is NOT symmetric). gemm2 reads H
// from a full smem copy (no serial L2 chain). Decoder phase (z, d1, B) runs
// at the end from L2-prefetched weights; CTA CSZ-1 builds the adj CSR.
template <int CSZ>
__global__ void __launch_bounds__(NT, 1)
pre_k(
    const float* __restrict__ x,   const int* __restrict__ ei,
    const float* __restrict__ adj,
    const float* __restrict__ W1,  const float* __restrict__ g1,  const float* __restrict__ be1,
    const float* __restrict__ W2,  const float* __restrict__ g2,  const float* __restrict__ be2,
    const float* __restrict__ Wmu, const float* __restrict__ bmu,
    const float* __restrict__ Wlv, const float* __restrict__ blv,
    const float* __restrict__ Wd1, const float* __restrict__ bd1,
    const float* __restrict__ Wd2, const float* __restrict__ bd2,
    const float* __restrict__ eps)
{
    constexpr int CPC = HID / CSZ;     // 16 (or 32)
    constexpr int CW  = CPC / 4;
    constexpr int STP = CPC + 1;
    constexpr int EPC = UTRI / CSZ;    // 285 (or 570) upper-tri entries per CTA

    extern __shared__ float sm[];
    float* At = sm;                    // 96*ATS: At[c*ATS+r] = A_norm[r][c]
    float* xs = At + N * ATS;          // 64*ATS: x^T staged
    float* sT = xs + IN_DIM * ATS;     // 96*STP
    float* sP = sT + 96 * STP;         // 96*STP
    float* sH = sP + 96 * STP;         // 96*256: full H copy for gemm2
    // decoder-phase overlays (At region is dead by then)
    float* sgv = At;                   // 256
    float* sz  = At + 256;             // 64
    float* sd1 = At + 320;             // 256
    float* smu = At + 576;             // 4*64
    float* slv = At + 832;             // 4*64

    __shared__ float stmp[N];

    const int t    = threadIdx.x;
    const int bid  = blockIdx.x;
    const int lane = t & 31, wid = t >> 5;
    const int r    = t % 96, g = t / 96;
    const int lc   = g * CW;
    const int gcol = bid * CPC + lc;

    // ---- warm L2 (fire-and-forget): GCN + head + decoder weights ---------
    if (t < IN_DIM) PREF_L2(&W1[t * HID + bid * CPC]);
    if (t < HID)    PREF_L2(&W2[t * HID + bid * CPC]);
    #pragma unroll
    for (int j = 0; j < 2; j++) {               // Wmu/Wlv/Wd1: 512 lines each
        int i = t + j * NT;
        if (i < 512) {
            PREF_L2(&Wmu[i * 32]);
            PREF_L2(&Wlv[i * 32]);
            PREF_L2(&Wd1[i * 32]);
        }
    }
    #pragma unroll
    for (int j = 0; j < 6; j++) {               // Wd2 slice: 256 rows x 9 lines
        int i = t + j * NT;
        if (i < 2304) {
            int row = i / 9, ln = i - row * 9;
            PREF_L2(&Wd2[row * NUM_LOGITS + bid * EPC + ln * 32]);
        }
    }

    // ---- build A_norm^T locally (replicated; ~1us) ------------------------
    for (int i = t; i < N * ATS; i += NT) At[i] = 0.f;
    __syncthreads();
    for (int e = t; e < E; e += NT) {
        int s = ei[e], d = ei[E + e];
        At[d * ATS + s] = 1.f;                    // A[s][d]=1 (same-value races OK)
    }
    if (t < N) At[t * ATS + t] = 1.f;             // A = max(A, I)
    for (int i = t; i < N * IN_DIM; i += NT) {    // stage x^T (disjoint region)
        int rr = i >> 6, k = i & 63;
        xs[k * ATS + rr] = x[i];
    }
    __syncthreads();
    if (t < N) {                                  // row sums of A (axis 1)
        float s = 0.f;
        #pragma unroll 4
        for (int d = 0; d < N; d++) s += At[d * ATS + t];
        stmp[t] = rsqrtf(s);
    }
    __syncthreads();
    for (int e = t; e < NN; e += NT) {            // A_norm = A*dinv_r*dinv_c
        int cc = e / N, rr = e - cc * N;
        At[cc * ATS + rr] *= stmp[rr] * stmp[cc];
    }
    {   // gemm1: T1 = x @ W1 (bias b1 exactly cancelled by BN)
        float acc[CW];
        #pragma unroll
        for (int c = 0; c < CW; c++) acc[c] = 0.f;
        #pragma unroll 8
        for (int k = 0; k < IN_DIM; k++) {
            float xv = xs[k * ATS + r];
            #pragma unroll
            for (int c4 = 0; c4 < CW / 4; c4++) {
                float4 w = *(const float4*)&W1[k * HID + gcol + 4 * c4];
                acc[4*c4+0] += xv * w.x; acc[4*c4+1] += xv * w.y;
                acc[4*c4+2] += xv * w.z; acc[4*c4+3] += xv * w.w;
            }
        }
        #pragma unroll
        for (int c = 0; c < CW; c++) sT[r * STP + lc + c] = acc[c];
    }
    __syncthreads();

    auto gcnbn = [&](const float* gamma, const float* beta, bool writeH, bool dogv) {
        float acc[CW];
        #pragma unroll
        for (int c = 0; c < CW; c++) acc[c] = 0.f;
        #pragma unroll 4
        for (int j = 0; j < N; j++) {
            float a = At[j * ATS + r];            // A_norm[r][j] (true row)
            #pragma unroll
            for (int c = 0; c < CW; c++)
                acc[c] += a * sT[j * STP + lc + c];
        }
        #pragma unroll
        for (int c = 0; c < CW; c++) sP[r * STP + lc + c] = acc[c];
        __syncthreads();
        for (int cc = wid; cc < CPC; cc += 12) {  // warp-per-column BN
            int col = bid * CPC + cc;
            float v0 = sP[lane * STP + cc];
            float v1 = sP[(lane + 32) * STP + cc];
            float v2 = sP[(lane + 64) * STP + cc];
            float s = v0 + v1 + v2, qd = v0*v0 + v1*v1 + v2*v2;
            #pragma unroll
            for (int o = 16; o; o >>= 1) {
                s  += __shfl_xor_sync(~0u, s, o);
                qd += __shfl_xor_sync(~0u, qd, o);
            }
            float m   = s * (1.f / N);
            float var = qd * (1.f / N) - m * m;
            float inv = rsqrtf(var + 1e-5f) * gamma[col];
            float bb  = beta[col];
            float h0 = fmaxf((v0 - m) * inv + bb, 0.f);
            float h1 = fmaxf((v1 - m) * inv + bb, 0.f);
            float h2 = fmaxf((v2 - m) * inv + bb, 0.f);
            if (writeH) {                          // transposed -> coalesced
                g_Ht[col * 96 + lane]      = h0;
                g_Ht[col * 96 + lane + 32] = h1;
                g_Ht[col * 96 + lane + 64] = h2;
            }
            if (dogv) {
                float gs = h0 + h1 + h2;
                #pragma unroll
                for (int o = 16; o; o >>= 1) gs += __shfl_xor_sync(~0u, gs, o);
                if (lane == 0) g_gv[col] = gs * (1.f / N);
            }
        }
    };

    gcnbn(g1, be1, true, false);     // layer 1 -> g_Ht
    CSYNC();                         // #1: g_Ht exchange

    // stage the FULL H into smem (coalesced float4, high MLP)
    for (int i4 = t; i4 < (HID * 96) / 4; i4 += NT)
        ((float4*)sH)[i4] = ((const float4*)g_Ht)[i4];
    __syncthreads();
    {   // gemm2: T2 = H @ W2 — inner loop all-smem now
        float acc[CW];
        #pragma unroll
        for (int c = 0; c < CW; c++) acc[c] = 0.f;
        #pragma unroll 8
        for (int k = 0; k < HID; k++) {
            float hv = sH[k * 96 + r];
            #pragma unroll
            for (int c4 = 0; c4 < CW / 4; c4++) {
                float4 w = *(const float4*)&W2[k * HID + gcol + 4 * c4];
                acc[4*c4+0] += hv * w.x; acc[4*c4+1] += hv * w.y;
                acc[4*c4+2] += hv * w.z; acc[4*c4+3] += hv * w.w;
            }
        }
        __syncthreads();
        #pragma unroll
        for (int c = 0; c < CW; c++) sT[r * STP + lc + c] = acc[c];
    }
    __syncthreads();
    gcnbn(g2, be2, false, true);     // layer 2 -> g_gv
    CSYNC();                         // #2: g_gv exchange

    // ==================== decoder phase (At region reused) =================
    // CTA CSZ-1: build adj_gt neighbor CSR concurrently (ballot compaction)
    if (bid == CSZ - 1) {
        for (int rr = wid; rr < N; rr += 12) {
            float a0 = adj[rr * N + lane];
            float a1 = adj[rr * N + 32 + lane];
            float a2 = adj[rr * N + 64 + lane];
            unsigned m0 = __ballot_sync(~0u, a0 > 0.5f);
            unsigned m1 = __ballot_sync(~0u, a1 > 0.5f);
            unsigned m2 = __ballot_sync(~0u, a2 > 0.5f);
            int c0 = __popc(m0), c1 = __popc(m1);
            unsigned lt = (1u << lane) - 1u;
            if (a0 > 0.5f) g_nbr[rr * N + __popc(m0 & lt)] = lane;
            if (a1 > 0.5f) g_nbr[rr * N + c0 + __popc(m1 & lt)] = lane + 32;
            if (a2 > 0.5f) g_nbr[rr * N + c0 + c1 + __popc(m2 & lt)] = lane + 64;
            if (lane == 0) {
                int dg = c0 + c1 + __popc(m2);
                g_deg[rr]  = dg;
                g_degA[rr] = (float)dg + 1.f;     // Agt diag forced to 1
            }
        }
    }

    if (t < HID) sgv[t] = g_gv[t];
    __syncthreads();
    if (t < HID) {                   // mu/lv: 4-way k-split over 256 threads
        int gg = t >> 6, cI = t & 63;
        float pm = 0.f, pl = 0.f;
        #pragma unroll 8
        for (int k = gg * 64; k < gg * 64 + 64; k++) {
            float gv = sgv[k];
            pm += gv * Wmu[k * ZD + cI];
            pl += gv * Wlv[k * ZD + cI];
        }
        smu[t] = pm; slv[t] = pl;    // laid out [gg*64 + cI]
    }
    __syncthreads();
    if (t < ZD) {
        float mu = bmu[t] + smu[t] + smu[64 + t] + smu[128 + t] + smu[192 + t];
        float lv = blv[t] + slv[t] + slv[64 + t] + slv[128 + t] + slv[192 + t];
        lv = fminf(fmaxf(lv, -4.f), 4.f);
        sz[t] = mu + eps[t] * expf(0.5f * lv);
    }
    __syncthreads();
    if (t < HID) {                   // d1 = relu(z @ Wd1 + bd1)
        float a = bd1[t];
        #pragma unroll 8
        for (int d = 0; d < ZD; d++) a += sz[d] * Wd1[d * HID + t];
        sd1[t] = fmaxf(a, 0.f);
    }
    __syncthreads();

    // B entries: this CTA's EPC consecutive upper-tri entries, full k2 loop
    for (int u = bid * EPC + t; u < (bid + 1) * EPC; u += NT) {
        float a = bd2[u];
        #pragma unroll 16
        for (int k2 = 0; k2 < HID; k2++)
            a += sd1[k2] * Wd2[k2 * NUM_LOGITS + u];   // L2-warm, coalesced
        int uu = u, rr = 0, rem = N - 1;
        while (uu >= rem) { uu -= rem; rem--; rr++; }
        int cc = rr + 1 + uu;
        float th  = tanhf(a);
        float sig = 1.f / (1.f + expf(-th));
        g_B[rr * N + cc] = sig;                        // B IS symmetric
        g_B[cc * N + rr] = sig;
    }
    if (bid == 0 && t < N) g_B[t * (N + 1)] = 1.f;     // diag = 1
}

// ============================= MPM KERNEL ==================================
// (verbatim proven version) Startup computes B stats / nd locally. M0 never
// materialized (all rows identical). Gather: 16 fully-unrolled independent
// ldcg (zero-row padding) + rare dynamic tail. F positively homogeneous:
// exact uniform rescale every 4 iters; final norm exact.
template <int CSZ>
__global__ void __launch_bounds__(NT2, 1)
mpm_k(float* __restrict__ out)
{
    constexpr int RPB = N / CSZ;
    constexpr int XE  = RPB * N;

    __shared__ __align__(16) float sX[XE];
    __shared__ float sND[XE];
    __shared__ float sdb[N];
    __shared__ float sm0[N];
    __shared__ int   snbroff[RPB * DMAX];
    __shared__ int   sdegp[RPB];
    __shared__ int   sdegr[RPB];
    __shared__ float red[24];

    const int t    = threadIdx.x;
    const int bid  = blockIdx.x;
    const int lane = t & 31, wid = t >> 5;
    const int q    = t >> 3;
    const int c    = t & 7;
    const int gbase = bid * XE;

    for (int row = wid; row < N; row += 24) {
        float b0 = g_B[row * N + lane];
        float b1 = g_B[row * N + lane + 32];
        float b2 = g_B[row * N + lane + 64];
        float s  = b0 + b1 + b2;
        float m  = fmaxf(fmaxf((lane == row) ? 0.f : b0,
                               (lane + 32 == row) ? 0.f : b1),
                               (lane + 64 == row) ? 0.f : b2);
        #pragma unroll
        for (int o = 16; o; o >>= 1) {
            s = s + __shfl_xor_sync(~0u, s, o);
            m = fmaxf(m, __shfl_xor_sync(~0u, m, o));
        }
        if (lane == 0) { sdb[row] = s; sm0[row] = m * (1.f / N); }
    }
    for (int e = t; e < RPB * DMAX; e += NT2) {
        int rw = e / DMAX, m = e % DMAX;
        int dg = g_deg[bid * RPB + rw];
        dg = (dg > DMAX) ? DMAX : dg;
        snbroff[e] = (m < dg) ? g_nbr[(bid * RPB + rw) * N + m] * N : NN;
        if (m == 0) { sdegp[rw] = (dg + 3) & ~3; sdegr[rw] = dg; }
    }
    if (t < N) { __stcg(&g_M[0][NN + t], 0.f); __stcg(&g_M[1][NN + t], 0.f); }
    float Breg[12];
    #pragma unroll
    for (int j = 0; j < 12; j++) {
        int l = 12 * c + j;
        Breg[j] = (l == q) ? 0.f : g_B[l * N + q];
    }
    __syncthreads();
    for (int e = t; e < XE; e += NT2) {
        int rw = e / 96;
        sX[e]  = 1.f / N;
        sND[e] = 1.f / (fabsf(g_degA[bid * RPB + rw] - sdb[e % 96]) + 1.f);
    }
    __syncthreads();

    for (int it = 0; it < ITERS; it++) {
        const float* __restrict__ Min  = g_M[it & 1];
        float*       __restrict__ Mout = g_M[(it + 1) & 1];

        float scale = 1.f;
        if (it > 0 && (it & 3) == 0) {
            float p = (lane < CSZ) ? __ldcg(&g_part[lane]) : 0.f;
            p += __shfl_xor_sync(~0u, p, 8);
            p += __shfl_xor_sync(~0u, p, 4);
            p += __shfl_xor_sync(~0u, p, 2);
            p += __shfl_xor_sync(~0u, p, 1);
            scale = rsqrtf(__shfl_sync(~0u, p, 0));
        }
        const bool last = (it == ITERS - 1);
        const bool pub  = ((it & 3) == 3) || last;

        float sq = 0.f;
        for (int e = t; e < XE; e += NT2) {
            int rw = e / 96, col = e % 96;
            float raw = sX[e] * sND[e];
            if (it == 0) {
                raw += (float)sdegr[rw] * sm0[col];
            } else {
                const int* off = &snbroff[rw * DMAX];
                float a0  = __ldcg(&Min[off[0]  + col]);
                float a1  = __ldcg(&Min[off[1]  + col]);
                float a2  = __ldcg(&Min[off[2]  + col]);
                float a3  = __ldcg(&Min[off[3]  + col]);
                float a4  = __ldcg(&Min[off[4]  + col]);
                float a5  = __ldcg(&Min[off[5]  + col]);
                float a6  = __ldcg(&Min[off[6]  + col]);
                float a7  = __ldcg(&Min[off[7]  + col]);
                float a8  = __ldcg(&Min[off[8]  + col]);
                float a9  = __ldcg(&Min[off[9]  + col]);
                float a10 = __ldcg(&Min[off[10] + col]);
                float a11 = __ldcg(&Min[off[11] + col]);
                float a12 = __ldcg(&Min[off[12] + col]);
                float a13 = __ldcg(&Min[off[13] + col]);
                float a14 = __ldcg(&Min[off[14] + col]);
                float a15 = __ldcg(&Min[off[15] + col]);
                raw += (((a0 + a1) + (a2 + a3)) + ((a4 + a5) + (a6 + a7)))
                     + (((a8 + a9) + (a10 + a11)) + ((a12 + a13) + (a14 + a15)));
                int dp = sdegp[rw];
                for (int m = 16; m < dp; m += 4) {
                    raw += __ldcg(&Min[off[m]     + col])
                         + __ldcg(&Min[off[m + 1] + col])
                         + __ldcg(&Min[off[m + 2] + col])
                         + __ldcg(&Min[off[m + 3] + col]);
                }
            }
            float v = raw * scale;
            sX[e] = v;
            if (pub) sq += v * v;
        }
        if (pub) {
            #pragma unroll
            for (int o = 16; o; o >>= 1) sq += __shfl_xor_sync(~0u, sq, o);
            if (lane == 0) red[wid] = sq;
        }
        __syncthreads();
        if (pub && t == 0) {
            float s2 = 0.f;
            #pragma unroll
            for (int w = 0; w < 24; w++) s2 += red[w];
            __stcg(&g_part[bid], s2);
        }

        if (!last) {
            #pragma unroll
            for (int r2 = 0; r2 < RPB; r2++) {
                const float4* xp = (const float4*)&sX[r2 * N + 12 * c];
                float4 x0 = xp[0], x1 = xp[1], x2 = xp[2];
                float ma, mb;
                ma =           Breg[0]  * x0.x;  mb =           Breg[1]  * x0.y;
                ma = fmaxf(ma, Breg[2]  * x0.z); mb = fmaxf(mb, Breg[3]  * x0.w);
                ma = fmaxf(ma, Breg[4]  * x1.x); mb = fmaxf(mb, Breg[5]  * x1.y);
                ma = fmaxf(ma, Breg[6]  * x1.z); mb = fmaxf(mb, Breg[7]  * x1.w);
                ma = fmaxf(ma, Breg[8]  * x2.x); mb = fmaxf(mb, Breg[9]  * x2.y);
                ma = fmaxf(ma, Breg[10] * x2.z); mb = fmaxf(mb, Breg[11] * x2.w);
                float m = fmaxf(ma, mb);
                m = fmaxf(m, __shfl_down_sync(~0u, m, 4));
                m = fmaxf(m, __shfl_down_sync(~0u, m, 2));
                m = fmaxf(m, __shfl_down_sync(~0u, m, 1));
                if (c == 0) __stcg(&Mout[gbase + r2 * N + q], m);
            }
        }
        CSYNC();
    }

    {
        float p = (lane < CSZ) ? __ldcg(&g_part[lane]) : 0.f;
        p += __shfl_xor_sync(~0u, p, 8);
        p += __shfl_xor_sync(~0u, p, 4);
        p += __shfl_xor_sync(~0u, p, 2);
        p += __shfl_xor_sync(~0u, p, 1);
        float os = rsqrtf(__shfl_sync(~0u, p, 0));
        for (int e = t; e < XE; e += NT2)
            out[gbase + e] = sX[e] * os;
    }
}

// ---------------- launch ----------------
extern "C" void kernel_launch(void* const* d_in, const int* in_sizes, int n_in,
                              void* d_out, int out_size) {
    const float* x   = (const float*)d_in[0];
    const int*   ei  = (const int*)  d_in[1];
    const float* adj = (const float*)d_in[2];
    const float* W1  = (const float*)d_in[3];
    // d_in[4] = b1 (cancelled by BN)
    const float* g1  = (const float*)d_in[5];
    const float* be1 = (const float*)d_in[6];
    const float* W2  = (const float*)d_in[7];
    // d_in[8] = b2 (cancelled by BN)
    const float* g2  = (const float*)d_in[9];
    const float* be2 = (const float*)d_in[10];
    const float* Wmu = (const float*)d_in[11];
    const float* bmu = (const float*)d_in[12];
    const float* Wlv = (const float*)d_in[13];
    const float* blv = (const float*)d_in[14];
    const float* Wd1 = (const float*)d_in[15];
    const float* bd1 = (const float*)d_in[16];
    const float* Wd2 = (const float*)d_in[17];
    const float* bd2 = (const float*)d_in[18];
    const float* eps = (const float*)d_in[19];
    float* o = (float*)d_out;

    // smem: A_norm^T + x^T + sT/sP + full-H copy
    const size_t sh16 = (size_t)((N + IN_DIM) * ATS + 2 * 96 * 17 + 96 * HID) * sizeof(float);
    const size_t sh8  = (size_t)((N + IN_DIM) * ATS + 2 * 96 * 33 + 96 * HID) * sizeof(float);

    cudaFuncSetAttribute(pre_k<16>,  cudaFuncAttributeNonPortableClusterSizeAllowed, 1);
    cudaFuncSetAttribute(mpm_k<16>,  cudaFuncAttributeNonPortableClusterSizeAllowed, 1);
    cudaFuncSetAttribute(pre_k<16>,  cudaFuncAttributeMaxDynamicSharedMemorySize, (int)sh16);
    cudaFuncSetAttribute(pre_k<8>,   cudaFuncAttributeMaxDynamicSharedMemorySize, (int)sh8);

    cudaLaunchAttribute at16[1];
    at16[0].id = cudaLaunchAttributeClusterDimension;
    at16[0].val.clusterDim = {16, 1, 1};

    cudaLaunchConfig_t cfgP16 = {};
    cfgP16.gridDim = dim3(16, 1, 1);
    cfgP16.blockDim = dim3(NT, 1, 1);
    cfgP16.dynamicSmemBytes = sh16;
    cfgP16.attrs = at16;  cfgP16.numAttrs = 1;

    cudaLaunchConfig_t cfgM16 = {};
    cfgM16.gridDim = dim3(16, 1, 1);
    cfgM16.blockDim = dim3(NT2, 1, 1);
    cfgM16.attrs = at16;  cfgM16.numAttrs = 1;

    int np = 0, nm = 0;
    cudaError_t e1 = cudaOccupancyMaxActiveClusters(&np, pre_k<16>, &cfgP16);
    cudaError_t e2 = cudaOccupancyMaxActiveClusters(&nm, mpm_k<16>, &cfgM16);
    if (e1 != cudaSuccess || e2 != cudaSuccess) { (void)cudaGetLastError(); np = nm = 0; }

    if (np >= 1 && nm >= 1) {
        cudaLaunchKernelEx(&cfgP16, pre_k<16>,
            x, ei, adj, W1, g1, be1, W2, g2, be2,
            Wmu, bmu, Wlv, blv, Wd1, bd1, Wd2, bd2, eps);
        cudaLaunchKernelEx(&cfgM16, mpm_k<16>, o);
    } else {
        cudaLaunchAttribute at8[1];
        at8[0].id = cudaLaunchAttributeClusterDimension;
        at8[0].val.clusterDim = {8, 1, 1};
        cudaLaunchConfig_t cfgP8 = {};
        cfgP8.gridDim = dim3(8, 1, 1);
        cfgP8.blockDim = dim3(NT, 1, 1);
        cfgP8.dynamicSmemBytes = sh8;
        cfgP8.attrs = at8;  cfgP8.numAttrs = 1;
        cudaLaunchConfig_t cfgM8 = {};
        cfgM8.gridDim = dim3(8, 1, 1);
        cfgM8.blockDim = dim3(NT2, 1, 1);
        cfgM8.attrs = at8;  cfgM8.numAttrs = 1;
        cudaLaunchKernelEx(&cfgP8, pre_k<8>,
            x, ei, adj, W1, g1, be1, W2, g2, be2,
            Wmu, bmu, Wlv, blv, Wd1, bd1, Wd2, bd2, eps);
        cudaLaunchKernelEx(&cfgM8, mpm_k<8>, o);
    }
}